// round 10
// baseline (speedup 1.0000x reference)
#include <cuda_runtime.h>

// Problem dims
#define T_DIM 2048
#define B_DIM 16
#define D_DIM 1024
#define N_DIM 64
#define C_DIM 256   // 4*N

// 32 MB scratch for the projected k/v/q/m sequence: (T, B, 4N)
__device__ float g_kvqm[(size_t)T_DIM * B_DIM * C_DIM];

// ---------------------------------------------------------------------------
// Kernel 1: kvqm[t,b,c] = sum_d x[t,b,d] * W[c,d]
// Treated as C(32768 x 256) = A(32768 x 1024) * W^T, both K-major (NT GEMM).
// Classic 128x128x16 SMEM-tiled fp32 GEMM, 8x8 per thread, reg-prefetched.
// ---------------------------------------------------------------------------
__global__ __launch_bounds__(256, 2)
void e80_gemm(const float* __restrict__ A, const float* __restrict__ W) {
    const int K  = D_DIM;   // 1024
    const int NC = C_DIM;   // 256
    const int BM = 128, BN = 128, BK = 16;

    __shared__ float As[BK][BM];
    __shared__ float Bs[BK][BN];

    const int tid   = threadIdx.x;
    const int mBase = blockIdx.y * BM;
    const int nBase = blockIdx.x * BN;

    // Global-load mapping: each thread loads 2 float4 per tile per operand.
    const int lr = tid >> 2;          // row within tile, 0..63 (and +64)
    const int kq = (tid & 3) * 4;     // k offset within BK: 0,4,8,12

    const float* Ag = A + (size_t)(mBase + lr) * K + kq;
    const float* Wg = W + (size_t)(nBase + lr) * K + kq;

    // Prefetch tile k0=0 into registers
    float4 pa0 = *(const float4*)(Ag);
    float4 pa1 = *(const float4*)(Ag + (size_t)64 * K);
    float4 pb0 = *(const float4*)(Wg);
    float4 pb1 = *(const float4*)(Wg + (size_t)64 * K);

    const int tx = tid & 15;   // N micro-tile
    const int ty = tid >> 4;   // M micro-tile

    float acc[8][8];
#pragma unroll
    for (int i = 0; i < 8; i++)
#pragma unroll
        for (int j = 0; j < 8; j++) acc[i][j] = 0.0f;

    for (int k0 = 0; k0 < K; k0 += BK) {
        // Stage prefetched registers into SMEM (transposed to [k][row])
        As[kq + 0][lr] = pa0.x; As[kq + 1][lr] = pa0.y;
        As[kq + 2][lr] = pa0.z; As[kq + 3][lr] = pa0.w;
        As[kq + 0][lr + 64] = pa1.x; As[kq + 1][lr + 64] = pa1.y;
        As[kq + 2][lr + 64] = pa1.z; As[kq + 3][lr + 64] = pa1.w;
        Bs[kq + 0][lr] = pb0.x; Bs[kq + 1][lr] = pb0.y;
        Bs[kq + 2][lr] = pb0.z; Bs[kq + 3][lr] = pb0.w;
        Bs[kq + 0][lr + 64] = pb1.x; Bs[kq + 1][lr + 64] = pb1.y;
        Bs[kq + 2][lr + 64] = pb1.z; Bs[kq + 3][lr + 64] = pb1.w;
        __syncthreads();

        // Prefetch next tile (hidden under the compute below)
        if (k0 + BK < K) {
            pa0 = *(const float4*)(Ag + k0 + BK);
            pa1 = *(const float4*)(Ag + (size_t)64 * K + k0 + BK);
            pb0 = *(const float4*)(Wg + k0 + BK);
            pb1 = *(const float4*)(Wg + (size_t)64 * K + k0 + BK);
        }

#pragma unroll
        for (int k = 0; k < BK; k++) {
            float ar[8], br[8];
            *(float4*)&ar[0] = *(const float4*)&As[k][ty * 8];
            *(float4*)&ar[4] = *(const float4*)&As[k][ty * 8 + 4];
            *(float4*)&br[0] = *(const float4*)&Bs[k][tx * 8];
            *(float4*)&br[4] = *(const float4*)&Bs[k][tx * 8 + 4];
#pragma unroll
            for (int i = 0; i < 8; i++)
#pragma unroll
                for (int j = 0; j < 8; j++)
                    acc[i][j] = fmaf(ar[i], br[j], acc[i][j]);
        }
        __syncthreads();
    }

    // Epilogue: vectorized stores to g_kvqm
#pragma unroll
    for (int i = 0; i < 8; i++) {
        float* Cp = g_kvqm + (size_t)(mBase + ty * 8 + i) * NC + nBase + tx * 8;
        *(float4*)Cp       = make_float4(acc[i][0], acc[i][1], acc[i][2], acc[i][3]);
        *(float4*)(Cp + 4) = make_float4(acc[i][4], acc[i][5], acc[i][6], acc[i][7]);
    }
}

// ---------------------------------------------------------------------------
// Kernel 2: the gated two-level scan.
// One warp per (batch b, row i) of the 64x64 states. Lane owns columns
// j = {2*lane, 2*lane+1}. S, M, B_S, B_M rows live in registers. No barriers
// in the time loop; next-step inputs are register-prefetched.
// ---------------------------------------------------------------------------
__device__ __forceinline__ float warp_sum(float p) {
#pragma unroll
    for (int off = 16; off > 0; off >>= 1)
        p += __shfl_xor_sync(0xffffffffu, p, off);
    return p;
}

__global__ __launch_bounds__(256)
void e80_scan(const float* __restrict__ S0,
              const float* __restrict__ M0,
              const float* __restrict__ B_S,
              const float* __restrict__ B_M,
              float* __restrict__ out, int out_size) {
    const int warp = threadIdx.x >> 5;
    const int lane = threadIdx.x & 31;
    const int row  = blockIdx.x * 8 + warp;   // 0..1023
    const int b    = row >> 6;
    const int i    = row & 63;

    // Per-lane persistent state: two columns each of S, M, and the biases.
    float2 bs2 = ((const float2*)(B_S + i * N_DIM))[lane];
    float2 bm2 = ((const float2*)(B_M + i * N_DIM))[lane];
    float2 s   = ((const float2*)(S0 + (size_t)row * N_DIM))[lane];
    float2 ms  = ((const float2*)(M0 + (size_t)row * N_DIM))[lane];

    // Prefetch t = 0 inputs
    const float* p0 = g_kvqm + b * C_DIM;
    float2 k2 = ((const float2*)(p0      ))[lane];
    float2 q2 = ((const float2*)(p0 + 128))[lane];
    float2 m2 = ((const float2*)(p0 + 192))[lane];
    float  v  = p0[64 + i];

    for (int t = 0; t < T_DIM; t++) {
        // ---- prefetch t+1 (clamped) ----
        const int tn = (t + 1 < T_DIM) ? (t + 1) : t;
        const float* pn = g_kvqm + (size_t)tn * (B_DIM * C_DIM) + b * C_DIM;
        float2 nk = ((const float2*)(pn      ))[lane];
        float2 nq = ((const float2*)(pn + 128))[lane];
        float2 nm = ((const float2*)(pn + 192))[lane];
        float  nv = pn[64 + i];

        // ---- S gate: G_S = sigmoid(v_i*k_j + B_S) ----
        float vk0 = v * k2.x, vk1 = v * k2.y;
        float x0 = fmaxf(vk0 + bs2.x, -30.0f);   // clamp: avoid exp overflow
        float x1 = fmaxf(vk1 + bs2.y, -30.0f);
        float e0 = __expf(-x0), e1 = __expf(-x1);
        float d0 = 1.0f + e0,   d1 = 1.0f + e1;
        float r  = __fdividef(1.0f, d0 * d1);    // 1 RCP serves 2 sigmoids
        float g0 = r * d1,      g1 = r * d0;
        // S = G*S + (1-G)*vk  ==  vk + G*(S - vk)
        s.x = fmaf(g0, s.x - vk0, vk0);
        s.y = fmaf(g1, s.y - vk1, vk1);

        // ---- Sq = S @ q (warp allreduce over 64 cols) ----
        float Sq = warp_sum(fmaf(s.x, q2.x, s.y * q2.y));

        // ---- M gate: G_M = sigmoid(Sq*m_j + B_M) ----
        float sm0 = Sq * m2.x, sm1 = Sq * m2.y;
        float y0 = fmaxf(sm0 + bm2.x, -30.0f);
        float y1 = fmaxf(sm1 + bm2.y, -30.0f);
        float f0 = __expf(-y0), f1 = __expf(-y1);
        float c0 = 1.0f + f0,   c1 = 1.0f + f1;
        float rr = __fdividef(1.0f, c0 * c1);
        float h0 = rr * c1,     h1 = rr * c0;
        ms.x = fmaf(h0, ms.x - sm0, sm0);
        ms.y = fmaf(h1, ms.y - sm1, sm1);

        // ---- out = M @ q ----
        float o = warp_sum(fmaf(ms.x, q2.x, ms.y * q2.y));
        if (lane == 0)
            out[(size_t)(t * B_DIM + b) * N_DIM + i] = o;

        // rotate prefetched inputs
        k2 = nk; q2 = nq; m2 = nm; v = nv;
    }

    // Final states S_f, M_f, packed after outs (if the harness expects them)
    const int OUTS = T_DIM * B_DIM * N_DIM;            // 2097152
    const int STN  = B_DIM * N_DIM * N_DIM;            // 65536
    if (out_size >= OUTS + 2 * STN) {
        ((float2*)(out + OUTS + (size_t)row * N_DIM))[lane]       = s;
        ((float2*)(out + OUTS + STN + (size_t)row * N_DIM))[lane] = ms;
    }
}

// ---------------------------------------------------------------------------
// Launch
// ---------------------------------------------------------------------------
extern "C" void kernel_launch(void* const* d_in, const int* in_sizes, int n_in,
                              void* d_out, int out_size) {
    const float* x    = (const float*)d_in[0];   // (T, B, D)
    const float* S0   = (const float*)d_in[1];   // (B, N, N)
    const float* M0   = (const float*)d_in[2];   // (B, N, N)
    const float* W    = (const float*)d_in[3];   // (4N, D)
    const float* B_S  = (const float*)d_in[4];   // (N, N)
    const float* B_M  = (const float*)d_in[5];   // (N, N)
    float* out = (float*)d_out;

    // GEMM: 32768 x 256 output, 128x128 tiles -> grid (2, 256)
    dim3 ggrid(C_DIM / 128, (T_DIM * B_DIM) / 128);
    e80_gemm<<<ggrid, 256>>>(x, W);

    // Scan: 1024 rows, 8 warps/CTA -> 128 CTAs
    e80_scan<<<128, 256>>>(S0, M0, B_S, B_M, out, out_size);
}